// round 16
// baseline (speedup 1.0000x reference)
#include <cuda_runtime.h>
#include <cstdint>

// ---------------------------------------------------------------------------
// Router: r[b,e] = || W[e] @ x[b] ||_2
//   x: [8192,4096] f32, W: [16,64,4096] f32, out: [8192,16] f32
// GEMM C = X @ W^T via mma.sync.m16n8k16.bf16 (base sm_103 target).
// R16 vs R15 (219.6us = 31 prep + 188 GEMM, tensor 59.7%): remaining ~76us
// is per-iteration barrier/load exposure shared by the single resident CTA.
// -> 2 CTAs/SM so one CTA's MMAs hide the other's barrier stalls:
// BM=128, BN=128, BK=64, 2 stages = 96KB/CTA, launch_bounds(256,2).
// Inner loop is R13/R15's proven shape (RSB=192 conflict-free, k-slot-remap
// LDS.128 feeding both m16n8k16 instances). Warp tile 64x32 (half expert)
// -> 2KB smem cross-warp reduction in the epilogue. Prep unchanged.
// ---------------------------------------------------------------------------

#define BDIM   8192
#define DDIM   4096
#define EDIM   16
#define NTOT   1024
#define BM     128
#define BN     128
#define BK     64                      /* bf16 cols per stage = 128B/row    */
#define STAGES 2
#define KT     (DDIM / BK)             /* 64 mainloop iterations            */
#define RSB    192                     /* smem row stride (=64 mod 128:
                                          conflict-free 16B phases)          */
#define A_BYTES (BM * RSB)             /* 24576 */
#define B_BYTES (BN * RSB)             /* 24576 */
#define STG_BYTES (A_BYTES + B_BYTES)  /* 49152 */
#define SMEM_BYTES (STAGES * STG_BYTES)/* 98304 -> 2 CTAs/SM                */

#define NX16 ((size_t)BDIM * DDIM / 16)
#define NW16 ((size_t)NTOT * DDIM / 16)

// bf16 scratch copies of the inputs (module-scope __device__ = legal scratch)
__device__ uint4 g_xb[(size_t)BDIM * DDIM / 8];   // 67 MB
__device__ uint4 g_wb[(size_t)NTOT * DDIM / 8];   //  8.4 MB

__device__ __forceinline__ void mma_bf16(float c[4],
                                         uint32_t a0, uint32_t a1,
                                         uint32_t a2, uint32_t a3,
                                         uint32_t b0, uint32_t b1) {
    asm volatile(
        "mma.sync.aligned.m16n8k16.row.col.f32.bf16.bf16.f32 "
        "{%0,%1,%2,%3}, {%4,%5,%6,%7}, {%8,%9}, {%0,%1,%2,%3};"
        : "+f"(c[0]), "+f"(c[1]), "+f"(c[2]), "+f"(c[3])
        : "r"(a0), "r"(a1), "r"(a2), "r"(a3), "r"(b0), "r"(b1));
}

__device__ __forceinline__ void cp16(uint32_t dst, const void* src) {
    asm volatile("cp.async.cg.shared.global [%0], [%1], 16;"
                 :: "r"(dst), "l"(src) : "memory");
}

__device__ __forceinline__ uint32_t pack_bf16x2(float lo, float hi) {
    uint32_t r;
    asm("cvt.rn.bf16x2.f32 %0, %1, %2;" : "=r"(r) : "f"(hi), "f"(lo));
    return r;
}

// ---------------------------------------------------------------------------
// Fused prep: f32 -> bf16 (RN, unbiased) for x and w in one launch.
// ---------------------------------------------------------------------------
__global__ void prep_xw(const float4* __restrict__ x,
                        const float4* __restrict__ w) {
    size_t i = (size_t)blockIdx.x * blockDim.x + threadIdx.x;
    const float4* src;
    uint4* dst;
    if (i < NX16) {
        src = x + 4 * i;              dst = g_xb + 2 * i;
    } else {
        size_t j = i - NX16;
        if (j >= NW16) return;
        src = w + 4 * j;              dst = g_wb + 2 * j;
    }
    float4 v0 = src[0], v1 = src[1], v2 = src[2], v3 = src[3];
    uint4 o0, o1;
    o0.x = pack_bf16x2(v0.x, v0.y);
    o0.y = pack_bf16x2(v0.z, v0.w);
    o0.z = pack_bf16x2(v1.x, v1.y);
    o0.w = pack_bf16x2(v1.z, v1.w);
    o1.x = pack_bf16x2(v2.x, v2.y);
    o1.y = pack_bf16x2(v2.z, v2.w);
    o1.z = pack_bf16x2(v3.x, v3.y);
    o1.w = pack_bf16x2(v3.z, v3.w);
    dst[0] = o0;
    dst[1] = o1;
}

// ---------------------------------------------------------------------------
// grid = (NTOT/BN = 8, BDIM/BM = 64) = 512 CTAs, n fastest (A L2 reuse).
// 8 warps: 2(m) x 4(n); warp tile 64x32 = half an expert per warp.
// ---------------------------------------------------------------------------
__global__ __launch_bounds__(256, 2)
void router_kernel(float* __restrict__ out) {
    extern __shared__ char smem[];
    __shared__ float red[BM][4];             // cross-warp expert partials

    const int tid  = threadIdx.x;
    const int lane = tid & 31;
    const int wid  = tid >> 5;
    const int wm   = wid & 1;                // 0..1 (64 m-rows each)
    const int wn   = wid >> 1;               // 0..3 (32 n-cols each)

    const int m_base = blockIdx.y * BM;
    const int n_base = blockIdx.x * BN;

    // ---- cp.async producer: thread -> (row = tid/8, 16B chunk = tid%8) ----
    const int lrow = tid >> 3;               // 0..31
    const int lch  = tid & 7;                // 0..7
    const char* gA = (const char*)g_xb
                   + ((size_t)(m_base + lrow) * DDIM + lch * 8) * 2;
    const char* gB = (const char*)g_wb
                   + ((size_t)(n_base + lrow) * DDIM + lch * 8) * 2;
    const uint32_t sbase = (uint32_t)__cvta_generic_to_shared(smem);
    const uint32_t sA0 = sbase + (uint32_t)(lrow * RSB + lch * 16);
    const uint32_t sB0 = sA0 + A_BYTES;

    auto load_stage = [&](int s, int kb /*bf16 col offset*/) {
        const uint32_t so = (uint32_t)(s * STG_BYTES);
        const char* ga = gA + (size_t)kb * 2;
#pragma unroll
        for (int p = 0; p < BM / 32; ++p)    // 4 passes of 32 rows
            cp16(sA0 + so + (uint32_t)(p * 32 * RSB),
                 ga + (size_t)(p * 32) * DDIM * 2);
        const char* gb = gB + (size_t)kb * 2;
#pragma unroll
        for (int p = 0; p < BN / 32; ++p)    // 4 passes of 32 rows
            cp16(sB0 + so + (uint32_t)(p * 32 * RSB),
                 gb + (size_t)(p * 32) * DDIM * 2);
    };

    load_stage(0, 0);
    asm volatile("cp.async.commit_group;" ::: "memory");

    float acc[4][4][4];
#pragma unroll
    for (int mt = 0; mt < 4; ++mt)
#pragma unroll
        for (int nt = 0; nt < 4; ++nt)
#pragma unroll
            for (int i = 0; i < 4; ++i) acc[mt][nt][i] = 0.f;

    const int g = lane >> 2;                 // group (row) id
    const int q = lane & 3;                  // quad id
    const char* Aw = smem + (wm * 64 + g) * RSB + q * 16;
    const char* Bw = smem + A_BYTES + (wn * 32 + g) * RSB + q * 16;

#pragma unroll 1
    for (int kt = 0; kt < KT; ++kt) {
        asm volatile("cp.async.wait_group 0;" ::: "memory");
        __syncthreads();

        if (kt + 1 < KT) load_stage((kt + 1) & 1, (kt + 1) * BK);
        asm volatile("cp.async.commit_group;" ::: "memory");

        const int cur = kt & 1;
        const char* Ac = Aw + cur * STG_BYTES;
        const char* Bc = Bw + cur * STG_BYTES;

#pragma unroll
        for (int c2 = 0; c2 < 2; ++c2) {     // two 32-col chunks per stage
            const int co = c2 * 64;
            uint4 al[4], ah[4];              // A rows g, g+8 per mt
#pragma unroll
            for (int mt = 0; mt < 4; ++mt) {
                const char* p = Ac + mt * 16 * RSB + co;
                al[mt] = *reinterpret_cast<const uint4*>(p);
                ah[mt] = *reinterpret_cast<const uint4*>(p + 8 * RSB);
            }
            uint4 bv[4];
#pragma unroll
            for (int nt = 0; nt < 4; ++nt)
                bv[nt] = *reinterpret_cast<const uint4*>(Bc + nt * 8 * RSB + co);

            // instance 0: fragment halves .x/.y — 16 independent acc chains
#pragma unroll
            for (int mt = 0; mt < 4; ++mt)
#pragma unroll
                for (int nt = 0; nt < 4; ++nt)
                    mma_bf16(acc[mt][nt],
                             al[mt].x, ah[mt].x, al[mt].y, ah[mt].y,
                             bv[nt].x, bv[nt].y);
            // instance 1: fragment halves .z/.w
#pragma unroll
            for (int mt = 0; mt < 4; ++mt)
#pragma unroll
                for (int nt = 0; nt < 4; ++nt)
                    mma_bf16(acc[mt][nt],
                             al[mt].z, ah[mt].z, al[mt].w, ah[mt].w,
                             bv[nt].z, bv[nt].w);
        }
    }

    // ---- epilogue ----------------------------------------------------------
    // Warp (wm, wn): sum of squares over its 32 n-cols, rows wm*64 + mt*16
    // + g (+8). red[row][wn]; expert el = wn>>1 (cols wn*32 within BN=128).
#pragma unroll
    for (int mt = 0; mt < 4; ++mt) {
        float s0 = 0.f, s1 = 0.f;
#pragma unroll
        for (int nt = 0; nt < 4; ++nt) {
            s0 = fmaf(acc[mt][nt][0], acc[mt][nt][0], s0);
            s0 = fmaf(acc[mt][nt][1], acc[mt][nt][1], s0);
            s1 = fmaf(acc[mt][nt][2], acc[mt][nt][2], s1);
            s1 = fmaf(acc[mt][nt][3], acc[mt][nt][3], s1);
        }
        s0 += __shfl_xor_sync(0xffffffffu, s0, 1);
        s0 += __shfl_xor_sync(0xffffffffu, s0, 2);
        s1 += __shfl_xor_sync(0xffffffffu, s1, 1);
        s1 += __shfl_xor_sync(0xffffffffu, s1, 2);
        if ((lane & 3) == 0) {
            const int row = wm * 64 + mt * 16 + g;
            red[row][wn]     = s0;
            red[row + 8][wn] = s1;
        }
    }
    __syncthreads();

    // 256 threads: rows 0..127 x experts 0..1
    {
        const int row = tid & 127;
        const int el  = tid >> 7;             // expert-local 0/1
        const float s = red[row][2 * el] + red[row][2 * el + 1];
        out[(size_t)(m_base + row) * EDIM + blockIdx.x * 2 + el] = sqrtf(s);
    }
}

// ---------------------------------------------------------------------------
extern "C" void kernel_launch(void* const* d_in, const int* in_sizes, int n_in,
                              void* d_out, int out_size) {
    (void)in_sizes; (void)n_in; (void)out_size;
    const float* x = (const float*)d_in[0];   // [8192, 4096]
    const float* w = (const float*)d_in[1];   // [16, 64, 4096]
    float* out = (float*)d_out;               // [8192, 16]

    const size_t total = NX16 + NW16;
    prep_xw<<<(unsigned)((total + 255) / 256), 256>>>(
        (const float4*)x, (const float4*)w);

    cudaFuncSetAttribute(router_kernel,
                         cudaFuncAttributeMaxDynamicSharedMemorySize, SMEM_BYTES);
    router_kernel<<<dim3(NTOT / BN, BDIM / BM), 256, SMEM_BYTES>>>(out);
}